// round 1
// baseline (speedup 1.0000x reference)
#include <cuda_runtime.h>
#include <math.h>

#define HH   512
#define NN   64
#define LL   4096
#define LF   2049
#define NTHR 512

__global__ __launch_bounds__(NTHR) void s4_kernel(
    const float* __restrict__ A_real,
    const float* __restrict__ A_imag,
    const float* __restrict__ Bm,
    const float* __restrict__ Cm,
    const float* __restrict__ Pm,
    const float* __restrict__ inv_dt,
    float* __restrict__ out)
{
    __shared__ float2 spec[LL];        // 32 KB: full Hermitian spectrum / FFT workspace
    __shared__ float2 tw[1025];        // 8.2 KB: exp(+i*pi*j/2048), j=0..1024 (quarter-fold)
    __shared__ float2 s_den[NN];       // (|A_dt|^2, -2*Re(A_dt))
    __shared__ float4 s_pq[2 * NN];    // (p00,q00,p01,q01),(p10,q10,p11,q11) per n

    const int h   = blockIdx.x;
    const int tid = threadIdx.x;

    // ---- twiddle table: W^j = exp(+2*pi*i*j/4096), j in [0,1024] ----
    for (int j = tid; j <= 1024; j += NTHR) {
        float ang = (float)j * (3.14159265358979323846f / 2048.0f);
        float s, c;
        sincosf(ang, &s, &c);
        tw[j] = make_float2(c, s);
    }

    // ---- per-(h,n) precompute (l-independent) ----
    if (tid < NN) {
        const int n  = tid;
        const float dt = expf(inv_dt[h]);
        const float ar = -expf(A_real[h * NN + n]) * dt;   // Re(A_dt)
        const float ai =  A_imag[h * NN + n] * dt;         // Im(A_dt)
        s_den[n] = make_float2(ar * ar + ai * ai, -2.0f * ar);

        const int base = (h * NN + n) * 2;
        const float bx = Bm[base], by = Bm[base + 1];
        const float cx = Cm[base], cy = Cm[base + 1];
        const float px = Pm[base], py = Pm[base + 1];

        // v_ab = Bcat_a * Ccat_b * dt ;  Bcat = [B, P], Ccat = [C, conj(P)]
        const float v00r = (bx * cx - by * cy) * dt, v00i = (bx * cy + by * cx) * dt;
        const float v01r = (bx * px + by * py) * dt, v01i = (by * px - bx * py) * dt;
        const float v10r = (px * cx - py * cy) * dt, v10i = (px * cy + py * cx) * dt;
        const float v11r = (px * px + py * py) * dt, v11i = 0.0f;

        // p = -2*(v_r*ar + v_i*ai) ; q = 2*v_r
        s_pq[2 * n] = make_float4(-2.0f * (v00r * ar + v00i * ai), 2.0f * v00r,
                                  -2.0f * (v01r * ar + v01i * ai), 2.0f * v01r);
        s_pq[2 * n + 1] = make_float4(-2.0f * (v10r * ar + v10i * ai), 2.0f * v10r,
                                      -2.0f * (v11r * ar + v11i * ai), 2.0f * v11r);
    }
    __syncthreads();

    // ---- Cauchy kernel: k_f[l] for l in [0, 2048], write Hermitian spectrum ----
    for (int l = tid; l < LF; l += NTHR) {
        const float ang = (float)l * (3.14159265358979323846f / 4096.0f);
        const float y  = 2.0f * tanf(ang);    // z = i*y
        const float y2 = y * y;

        float r00r = 0.f, r00i = 0.f, r01r = 0.f, r01i = 0.f;
        float r10r = 0.f, r10i = 0.f, r11r = 0.f, r11i = 0.f;

        #pragma unroll 8
        for (int n = 0; n < NN; n++) {
            const float2 den = s_den[n];
            const float dr = den.x - y2;          // |A|^2 - y^2
            const float di = den.y * y;           // -2*Re(A)*y
            const float inv = __fdividef(1.0f, dr * dr + di * di);
            const float u  = dr * inv;
            const float w  = di * inv;
            const float yu = y * u;
            const float yw = y * w;
            const float4 a = s_pq[2 * n];
            const float4 b = s_pq[2 * n + 1];
            // (p + i*q*y) * (dr - i*di) * inv
            r00r += a.x * u + a.y * yw;  r00i += a.y * yu - a.x * w;
            r01r += a.z * u + a.w * yw;  r01i += a.w * yu - a.z * w;
            r10r += b.x * u + b.y * yw;  r10i += b.y * yu - b.x * w;
            r11r += b.z * u + b.w * yw;  r11i += b.w * yu - b.z * w;
        }

        // k_f = (r00 - r01*r10/(1 + r11)) * (1 + i*y/2)
        const float cr = 1.0f + r11r, ci = r11i;
        const float cinv = __fdividef(1.0f, cr * cr + ci * ci);
        const float tr = r01r * r10r - r01i * r10i;
        const float ti = r01r * r10i + r01i * r10r;
        const float qr = (tr * cr + ti * ci) * cinv;
        const float qi = (ti * cr - tr * ci) * cinv;
        const float kr = r00r - qr;
        const float ki = r00i - qi;
        const float hy = 0.5f * y;
        float fr = kr - ki * hy;
        float fi = ki + kr * hy;
        if (l == 0 || l == LL / 2) fi = 0.0f;   // pocketfft c2r drops DC/Nyquist imag
        spec[l] = make_float2(fr, fi);
        if (l > 0 && l < LL / 2) spec[LL - l] = make_float2(fr, -fi);
    }
    __syncthreads();

    // ---- in-place inverse FFT (length 4096, sign +), bit-reversal DIT ----
    for (int i = tid; i < LL; i += NTHR) {
        const int r = __brev(i) >> 20;   // 32 - 12
        if (r > i) {
            float2 t = spec[i]; spec[i] = spec[r]; spec[r] = t;
        }
    }
    __syncthreads();

    for (int s = 1; s <= 12; s++) {
        const int half = 1 << (s - 1);
        const int tws  = 12 - s;
        for (int k = tid; k < LL / 2; k += NTHR) {
            const int j  = k & (half - 1);
            const int i0 = ((k >> (s - 1)) << s) + j;
            const int i1 = i0 + half;
            const int wi = j << tws;     // in [0, 2048)
            float2 w;
            if (wi <= 1024) {
                w = tw[wi];
            } else {                     // W^wi = i * W^(wi-1024)
                const float2 t = tw[wi - 1024];
                w = make_float2(-t.y, t.x);
            }
            const float2 a = spec[i0];
            const float2 b = spec[i1];
            const float trr = w.x * b.x - w.y * b.y;
            const float tii = w.x * b.y + w.y * b.x;
            spec[i0] = make_float2(a.x + trr, a.y + tii);
            spec[i1] = make_float2(a.x - trr, a.y - tii);
        }
        __syncthreads();
    }

    const float scale = 1.0f / (float)LL;
    for (int t = tid; t < LL; t += NTHR) {
        out[h * LL + t] = spec[t].x * scale;
    }
}

extern "C" void kernel_launch(void* const* d_in, const int* in_sizes, int n_in,
                              void* d_out, int out_size)
{
    (void)in_sizes; (void)n_in; (void)out_size;
    s4_kernel<<<HH, NTHR>>>(
        (const float*)d_in[0],   // A_real (H, N)
        (const float*)d_in[1],   // A_imag (H, N)
        (const float*)d_in[2],   // B (1, H, N, 2)
        (const float*)d_in[3],   // C (1, H, N, 2)
        (const float*)d_in[4],   // P (1, H, N, 2)
        (const float*)d_in[5],   // inv_dt (H,)
        (float*)d_out);          // (1, H, L) fp32
}

// round 2
// speedup vs baseline: 1.3440x; 1.3440x over previous
#include <cuda_runtime.h>
#include <math.h>

#define HH   512
#define NN   64
#define LL   4096
#define LF   2049
#define NTHR 256

typedef unsigned long long ull;

__device__ __forceinline__ ull f2_fma(ull a, ull b, ull c) {
    ull d; asm("fma.rn.f32x2 %0, %1, %2, %3;" : "=l"(d) : "l"(a), "l"(b), "l"(c)); return d;
}
__device__ __forceinline__ ull f2_mul(ull a, ull b) {
    ull d; asm("mul.rn.f32x2 %0, %1, %2;" : "=l"(d) : "l"(a), "l"(b)); return d;
}
__device__ __forceinline__ ull f2_add(ull a, ull b) {
    ull d; asm("add.rn.f32x2 %0, %1, %2;" : "=l"(d) : "l"(a), "l"(b)); return d;
}
__device__ __forceinline__ ull f2_pack(float lo, float hi) {
    ull d; asm("mov.b64 %0, {%1, %2};" : "=l"(d) : "f"(lo), "f"(hi)); return d;
}
__device__ __forceinline__ float2 f2_unpack(ull a) {
    float lo, hi; asm("mov.b64 {%0, %1}, %2;" : "=f"(lo), "=f"(hi) : "l"(a));
    return make_float2(lo, hi);
}
__device__ __forceinline__ float frcp(float x) {
    float r; asm("rcp.approx.f32 %0, %1;" : "=f"(r) : "f"(x)); return r;
}

__global__ __launch_bounds__(NTHR, 4) void s4_kernel(
    const float* __restrict__ A_real,
    const float* __restrict__ A_imag,
    const float* __restrict__ Bm,
    const float* __restrict__ Cm,
    const float* __restrict__ Pm,
    const float* __restrict__ inv_dt,
    float* __restrict__ out)
{
    __shared__ float2 spec[LL];          // 32 KB: Hermitian spectrum / FFT workspace
    __shared__ float2 tw[1025];          // 8.2 KB: exp(+i*pi*j/2048), j=0..1024
    __shared__ float4 s_coef[NN / 2][5]; // 2.5 KB: paired-n SoA coefficients

    const int h   = blockIdx.x;
    const int tid = threadIdx.x;

    // ---- twiddle table: W^j = exp(+2*pi*i*j/4096), j in [0,1024] ----
    for (int j = tid; j <= 1024; j += NTHR) {
        float ang = (float)j * (3.14159265358979323846f / 2048.0f);
        float s, c;
        sincosf(ang, &s, &c);
        tw[j] = make_float2(c, s);
    }

    // ---- per-(h,n) precompute (l-independent), written as n-pairs ----
    if (tid < NN) {
        const int n  = tid;
        const float dt = expf(inv_dt[h]);
        const float ar = -expf(A_real[h * NN + n]) * dt;   // Re(A_dt)
        const float ai =  A_imag[h * NN + n] * dt;         // Im(A_dt)

        const int base = (h * NN + n) * 2;
        const float bx = Bm[base], by = Bm[base + 1];
        const float cx = Cm[base], cy = Cm[base + 1];
        const float px = Pm[base], py = Pm[base + 1];

        // v_ab = Bcat_a * Ccat_b * dt ;  Bcat = [B, P], Ccat = [C, conj(P)]
        const float v00r = (bx * cx - by * cy) * dt, v00i = (bx * cy + by * cx) * dt;
        const float v01r = (bx * px + by * py) * dt, v01i = (by * px - bx * py) * dt;
        const float v10r = (px * cx - py * cy) * dt, v10i = (px * cy + py * cx) * dt;
        const float v11r = (px * px + py * py) * dt, v11i = 0.0f;

        float* c = (float*)&s_coef[n >> 1][0];
        const int o = n & 1;
        c[0  + o] = ar * ar + ai * ai;                // denx = |A_dt|^2
        c[2  + o] = -2.0f * ar;                       // deny = -2*Re(A_dt)
        c[4  + o] = -2.0f * (v00r * ar + v00i * ai);  // p00
        c[6  + o] =  2.0f * v00r;                     // q00
        c[8  + o] = -2.0f * (v01r * ar + v01i * ai);  // p01
        c[10 + o] =  2.0f * v01r;                     // q01
        c[12 + o] = -2.0f * (v10r * ar + v10i * ai);  // p10
        c[14 + o] =  2.0f * v10r;                     // q10
        c[16 + o] = -2.0f * (v11r * ar + v11i * ai);  // p11
        c[18 + o] =  2.0f * v11r;                     // q11
    }
    __syncthreads();

    // ---- Cauchy kernel: k_f[l], l in [0, 2048]; n packed 2-wide via f32x2 ----
    for (int l = tid; l < LF; l += NTHR) {
        // y = 2*tan(pi*l/4096) via half-angle from the twiddle table
        float y;
        if (l == 0) {
            y = 0.0f;
        } else if (l == LL / 2) {
            y = 2.0f * tanf((float)l * (3.14159265358979323846f / 4096.0f));
        } else if (l <= 1024) {
            const float2 t = tw[l];             // angle pi*l/2048
            y = 2.0f * __fdividef(t.y, 1.0f + t.x);
        } else {
            const float2 t = tw[2048 - l];      // cos(th) = -t.x, sin(th) = t.y
            y = 2.0f * __fdividef(1.0f + t.x, t.y);
        }

        const ull yd  = f2_pack(y, y);
        const float y2 = y * y;
        const ull ny2 = f2_pack(-y2, -y2);

        ull a00r = 0, a00i = 0, a01r = 0, a01i = 0;
        ull a10r = 0, a10i = 0, a11r = 0, a11i = 0;

        #pragma unroll 4
        for (int k = 0; k < NN / 2; k++) {
            const ulonglong2* cc = (const ulonglong2*)&s_coef[k][0];
            const ulonglong2 c0 = cc[0];   // (denx pair, deny pair)
            const ulonglong2 c1 = cc[1];   // (p00 pair,  q00 pair)
            const ulonglong2 c2 = cc[2];   // (p01 pair,  q01 pair)
            const ulonglong2 c3 = cc[3];   // (p10 pair,  q10 pair)
            const ulonglong2 c4 = cc[4];   // (p11 pair,  q11 pair)

            const ull dr  = f2_add(c0.x, ny2);          // |A|^2 - y^2
            const ull di  = f2_mul(c0.y, yd);           // -2*Re(A)*y
            const ull mag = f2_fma(di, di, f2_mul(dr, dr));
            const float2 m = f2_unpack(mag);
            const ull inv = f2_pack(frcp(m.x), frcp(m.y));
            const ull u   = f2_mul(dr, inv);
            const ull w   = f2_mul(di, inv);
            const ull yu  = f2_mul(yd, u);
            const ull yw  = f2_mul(yd, w);
            const ull nw  = w ^ 0x8000000080000000ULL;  // -w (both halves)

            // r = (p + i*q*y) / (dr + i*di):  re = p*u + q*yw,  im = q*yu - p*w
            a00r = f2_fma(c1.x, u,  a00r);  a00r = f2_fma(c1.y, yw, a00r);
            a00i = f2_fma(c1.y, yu, a00i);  a00i = f2_fma(c1.x, nw, a00i);
            a01r = f2_fma(c2.x, u,  a01r);  a01r = f2_fma(c2.y, yw, a01r);
            a01i = f2_fma(c2.y, yu, a01i);  a01i = f2_fma(c2.x, nw, a01i);
            a10r = f2_fma(c3.x, u,  a10r);  a10r = f2_fma(c3.y, yw, a10r);
            a10i = f2_fma(c3.y, yu, a10i);  a10i = f2_fma(c3.x, nw, a10i);
            a11r = f2_fma(c4.x, u,  a11r);  a11r = f2_fma(c4.y, yw, a11r);
            a11i = f2_fma(c4.y, yu, a11i);  a11i = f2_fma(c4.x, nw, a11i);
        }

        // horizontal sums over the two packed n's
        const float2 s00r = f2_unpack(a00r), s00i = f2_unpack(a00i);
        const float2 s01r = f2_unpack(a01r), s01i = f2_unpack(a01i);
        const float2 s10r = f2_unpack(a10r), s10i = f2_unpack(a10i);
        const float2 s11r = f2_unpack(a11r), s11i = f2_unpack(a11i);
        const float r00r = s00r.x + s00r.y, r00i = s00i.x + s00i.y;
        const float r01r = s01r.x + s01r.y, r01i = s01i.x + s01i.y;
        const float r10r = s10r.x + s10r.y, r10i = s10i.x + s10i.y;
        const float r11r = s11r.x + s11r.y, r11i = s11i.x + s11i.y;

        // k_f = (r00 - r01*r10/(1 + r11)) * (1 + i*y/2)
        const float cr = 1.0f + r11r, ci = r11i;
        const float cinv = frcp(cr * cr + ci * ci);
        const float trm = r01r * r10r - r01i * r10i;
        const float tim = r01r * r10i + r01i * r10r;
        const float qr = (trm * cr + tim * ci) * cinv;
        const float qi = (tim * cr - trm * ci) * cinv;
        const float kr = r00r - qr;
        const float ki = r00i - qi;
        const float hy = 0.5f * y;
        float fr = kr - ki * hy;
        float fi = ki + kr * hy;
        if (l == 0 || l == LL / 2) fi = 0.0f;   // pocketfft c2r drops DC/Nyquist imag
        spec[l] = make_float2(fr, fi);
        if (l > 0 && l < LL / 2) spec[LL - l] = make_float2(fr, -fi);
    }
    __syncthreads();

    // ---- in-place inverse FFT (length 4096, sign +): bit-reversal then fused radix-4 ----
    for (int i = tid; i < LL; i += NTHR) {
        const int r = __brev(i) >> 20;   // 32 - 12
        if (r > i) {
            float2 t = spec[i]; spec[i] = spec[r]; spec[r] = t;
        }
    }
    __syncthreads();

    // fuse stage pairs (s, s+1): s = 1,3,5,7,9,11
    for (int s = 1; s <= 11; s += 2) {
        const int hh   = 1 << (s - 1);
        const int tws2 = 11 - s;
        for (int q = tid; q < LL / 4; q += NTHR) {
            const int j    = q & (hh - 1);
            const int base = ((q >> (s - 1)) << (s + 1)) + j;
            const int i0 = base, i1 = base + hh, i2 = base + 2 * hh, i3 = base + 3 * hh;

            const float2 w2 = tw[j << tws2];               // W^(j*2^(11-s)), in [0,1024)
            const float w1x = w2.x * w2.x - w2.y * w2.y;   // w1 = w2^2
            const float w1y = 2.0f * w2.x * w2.y;

            const float2 x0 = spec[i0], x1 = spec[i1], x2 = spec[i2], x3 = spec[i3];

            // stage s (twiddle w1 on both sub-butterflies)
            const float t1x = w1x * x1.x - w1y * x1.y, t1y = w1x * x1.y + w1y * x1.x;
            const float a0x = x0.x + t1x, a0y = x0.y + t1y;
            const float a1x = x0.x - t1x, a1y = x0.y - t1y;
            const float t3x = w1x * x3.x - w1y * x3.y, t3y = w1x * x3.y + w1y * x3.x;
            const float a2x = x2.x + t3x, a2y = x2.y + t3y;
            const float a3x = x2.x - t3x, a3y = x2.y - t3y;

            // stage s+1: twiddles w2 and i*w2
            const float t2x = w2.x * a2x - w2.y * a2y, t2y = w2.x * a2y + w2.y * a2x;
            const float c3x = w2.x * a3x - w2.y * a3y, c3y = w2.x * a3y + w2.y * a3x;

            spec[i0] = make_float2(a0x + t2x, a0y + t2y);
            spec[i2] = make_float2(a0x - t2x, a0y - t2y);
            spec[i1] = make_float2(a1x - c3y, a1y + c3x);   // + i*c3
            spec[i3] = make_float2(a1x + c3y, a1y - c3x);   // - i*c3
        }
        __syncthreads();
    }

    const float scale = 1.0f / (float)LL;
    for (int t = tid; t < LL; t += NTHR) {
        out[h * LL + t] = spec[t].x * scale;
    }
}

extern "C" void kernel_launch(void* const* d_in, const int* in_sizes, int n_in,
                              void* d_out, int out_size)
{
    (void)in_sizes; (void)n_in; (void)out_size;
    s4_kernel<<<HH, NTHR>>>(
        (const float*)d_in[0],   // A_real (H, N)
        (const float*)d_in[1],   // A_imag (H, N)
        (const float*)d_in[2],   // B (1, H, N, 2)
        (const float*)d_in[3],   // C (1, H, N, 2)
        (const float*)d_in[4],   // P (1, H, N, 2)
        (const float*)d_in[5],   // inv_dt (H,)
        (float*)d_out);          // (1, H, L) fp32
}

// round 3
// speedup vs baseline: 1.6056x; 1.1947x over previous
#include <cuda_runtime.h>
#include <math.h>

#define HH 512
#define NN 64
#define LL 4096
#define MM 2048
#define LF 2049

typedef unsigned long long ull;

__device__ float2 g_X[HH * LF];   // Cauchy output spectrum X[h][l], l=0..2048

__device__ __forceinline__ ull f2_fma(ull a, ull b, ull c) {
    ull d; asm("fma.rn.f32x2 %0, %1, %2, %3;" : "=l"(d) : "l"(a), "l"(b), "l"(c)); return d;
}
__device__ __forceinline__ ull f2_mul(ull a, ull b) {
    ull d; asm("mul.rn.f32x2 %0, %1, %2;" : "=l"(d) : "l"(a), "l"(b)); return d;
}
__device__ __forceinline__ ull f2_add(ull a, ull b) {
    ull d; asm("add.rn.f32x2 %0, %1, %2;" : "=l"(d) : "l"(a), "l"(b)); return d;
}
__device__ __forceinline__ ull f2_pack(float lo, float hi) {
    ull d; asm("mov.b64 %0, {%1, %2};" : "=l"(d) : "f"(lo), "f"(hi)); return d;
}
__device__ __forceinline__ float2 f2_unpack(ull a) {
    float lo, hi; asm("mov.b64 {%0, %1}, %2;" : "=f"(lo), "=f"(hi) : "l"(a));
    return make_float2(lo, hi);
}
__device__ __forceinline__ float frcp(float x) {
    float r; asm("rcp.approx.f32 %0, %1;" : "=f"(r) : "f"(x)); return r;
}

// ============================================================================
// Kernel A: Cauchy sums -> X[h][l] for l in [0, 2048]
// grid (HH, 2), block 256. Block y handles l in [y*1024, y*1024+1024), plus
// (y==1, tid==0) handles l=2048.
// ============================================================================
__global__ __launch_bounds__(256) void s4_cauchy(
    const float* __restrict__ A_real,
    const float* __restrict__ A_imag,
    const float* __restrict__ Bm,
    const float* __restrict__ Cm,
    const float* __restrict__ Pm,
    const float* __restrict__ inv_dt)
{
    // per n-pair: 9 ulonglong2 = (m,c2),(p00,qc00),(q00,npc00),(p01,qc01),
    //             (q01,npc01),(p10,qc10),(q10,npc10),(p11,qc11),(q11,npc11)
    __shared__ ulonglong2 s_coef[NN / 2][9];

    const int h   = blockIdx.x;
    const int tid = threadIdx.x;

    if (tid < NN) {
        const int n  = tid;
        const float dt = expf(inv_dt[h]);
        const float ar = -expf(A_real[h * NN + n]) * dt;   // Re(A_dt)
        const float ai =  A_imag[h * NN + n] * dt;         // Im(A_dt)

        const int base = (h * NN + n) * 2;
        const float bx = Bm[base], by = Bm[base + 1];
        const float cx = Cm[base], cy = Cm[base + 1];
        const float px = Pm[base], py = Pm[base + 1];

        // v_ab = Bcat_a * Ccat_b * dt ; Bcat=[B,P], Ccat=[C,conj(P)]
        float vr[4], vi[4];
        vr[0] = (bx * cx - by * cy) * dt;  vi[0] = (bx * cy + by * cx) * dt;
        vr[1] = (bx * px + by * py) * dt;  vi[1] = (by * px - bx * py) * dt;
        vr[2] = (px * cx - py * cy) * dt;  vi[2] = (px * cy + py * cx) * dt;
        vr[3] = (px * px + py * py) * dt;  vi[3] = 0.0f;

        float* c = (float*)&s_coef[n >> 1][0];
        const int o = n & 1;
        const float ccoef = -2.0f * ar;                 // di = ccoef * y
        c[0 + o] = ar * ar + ai * ai;                   // m
        c[2 + o] = ccoef * ccoef;                       // c^2
        #pragma unroll
        for (int ab = 0; ab < 4; ab++) {
            const float p = -2.0f * (vr[ab] * ar + vi[ab] * ai);
            const float q =  2.0f * vr[ab];
            const int bo = 4 + ab * 8;
            c[bo + 0 + o] = p;
            c[bo + 2 + o] = q * ccoef;                  // qc
            c[bo + 4 + o] = q;
            c[bo + 6 + o] = -p * ccoef;                 // npc
        }
    }
    __syncthreads();

    const int base_l = blockIdx.y * 1024;
    const float ANG = 3.14159265358979323846f / 4096.0f;

    for (int pass = 0; pass < 3; pass++) {
        int l0, l1;
        bool store1 = true;
        if (pass < 2) {
            l0 = base_l + pass * 512 + tid;
            l1 = l0 + 256;
        } else {
            if (!(blockIdx.y == 1 && tid == 0)) break;
            l0 = 2048; l1 = 2048; store1 = false;       // tail bin
        }

        const float ya = 2.0f * tanf((float)l0 * ANG);
        const float yb = 2.0f * tanf((float)l1 * ANG);
        const ull y2a  = f2_pack(ya * ya, ya * ya);
        const ull y2b  = f2_pack(yb * yb, yb * yb);
        const ull ny2a = y2a ^ 0x8000000080000000ULL;
        const ull ny2b = y2b ^ 0x8000000080000000ULL;

        ull accra0 = 0, accia0 = 0, accra1 = 0, accia1 = 0;
        ull accra2 = 0, accia2 = 0, accra3 = 0, accia3 = 0;
        ull accrb0 = 0, accib0 = 0, accrb1 = 0, accib1 = 0;
        ull accrb2 = 0, accib2 = 0, accrb3 = 0, accib3 = 0;

        #pragma unroll 2
        for (int k = 0; k < NN / 2; k++) {
            const ulonglong2* cc = &s_coef[k][0];
            const ulonglong2 v0 = cc[0];                // (m, c2)

            // bin a setup
            const ull dra   = f2_add(v0.x, ny2a);
            const ull maga  = f2_fma(dra, dra, f2_mul(v0.y, y2a));
            const float2 ma = f2_unpack(maga);
            const ull inva  = f2_pack(frcp(ma.x), frcp(ma.y));
            const ull dinva = f2_mul(dra, inva);
            const ull y2iva = f2_mul(y2a, inva);
            // bin b setup
            const ull drb   = f2_add(v0.x, ny2b);
            const ull magb  = f2_fma(drb, drb, f2_mul(v0.y, y2b));
            const float2 mb = f2_unpack(magb);
            const ull invb  = f2_pack(frcp(mb.x), frcp(mb.y));
            const ull dinvb = f2_mul(drb, invb);
            const ull y2ivb = f2_mul(y2b, invb);

            const ulonglong2 c1 = cc[1], c2 = cc[2];    // ab=00: (p,qc),(q,npc)
            accra0 = f2_fma(c1.x, dinva, accra0); accra0 = f2_fma(c1.y, y2iva, accra0);
            accia0 = f2_fma(c2.x, dinva, accia0); accia0 = f2_fma(c2.y, inva,  accia0);
            accrb0 = f2_fma(c1.x, dinvb, accrb0); accrb0 = f2_fma(c1.y, y2ivb, accrb0);
            accib0 = f2_fma(c2.x, dinvb, accib0); accib0 = f2_fma(c2.y, invb,  accib0);

            const ulonglong2 c3 = cc[3], c4 = cc[4];    // ab=01
            accra1 = f2_fma(c3.x, dinva, accra1); accra1 = f2_fma(c3.y, y2iva, accra1);
            accia1 = f2_fma(c4.x, dinva, accia1); accia1 = f2_fma(c4.y, inva,  accia1);
            accrb1 = f2_fma(c3.x, dinvb, accrb1); accrb1 = f2_fma(c3.y, y2ivb, accrb1);
            accib1 = f2_fma(c4.x, dinvb, accib1); accib1 = f2_fma(c4.y, invb,  accib1);

            const ulonglong2 c5 = cc[5], c6 = cc[6];    // ab=10
            accra2 = f2_fma(c5.x, dinva, accra2); accra2 = f2_fma(c5.y, y2iva, accra2);
            accia2 = f2_fma(c6.x, dinva, accia2); accia2 = f2_fma(c6.y, inva,  accia2);
            accrb2 = f2_fma(c5.x, dinvb, accrb2); accrb2 = f2_fma(c5.y, y2ivb, accrb2);
            accib2 = f2_fma(c6.x, dinvb, accib2); accib2 = f2_fma(c6.y, invb,  accib2);

            const ulonglong2 c7 = cc[7], c8 = cc[8];    // ab=11
            accra3 = f2_fma(c7.x, dinva, accra3); accra3 = f2_fma(c7.y, y2iva, accra3);
            accia3 = f2_fma(c8.x, dinva, accia3); accia3 = f2_fma(c8.y, inva,  accia3);
            accrb3 = f2_fma(c7.x, dinvb, accrb3); accrb3 = f2_fma(c7.y, y2ivb, accrb3);
            accib3 = f2_fma(c8.x, dinvb, accib3); accib3 = f2_fma(c8.y, invb,  accib3);
        }

        // epilogue for each bin
        #pragma unroll
        for (int bsel = 0; bsel < 2; bsel++) {
            const float y = bsel ? yb : ya;
            const int   l = bsel ? l1 : l0;
            if (bsel && !store1) break;
            const float2 sr0 = f2_unpack(bsel ? accrb0 : accra0);
            const float2 si0 = f2_unpack(bsel ? accib0 : accia0);
            const float2 sr1 = f2_unpack(bsel ? accrb1 : accra1);
            const float2 si1 = f2_unpack(bsel ? accib1 : accia1);
            const float2 sr2 = f2_unpack(bsel ? accrb2 : accra2);
            const float2 si2 = f2_unpack(bsel ? accib2 : accia2);
            const float2 sr3 = f2_unpack(bsel ? accrb3 : accra3);
            const float2 si3 = f2_unpack(bsel ? accib3 : accia3);
            const float r00r = sr0.x + sr0.y, r00i = (si0.x + si0.y) * y;
            const float r01r = sr1.x + sr1.y, r01i = (si1.x + si1.y) * y;
            const float r10r = sr2.x + sr2.y, r10i = (si2.x + si2.y) * y;
            const float r11r = sr3.x + sr3.y, r11i = (si3.x + si3.y) * y;

            // k_f = (r00 - r01*r10/(1 + r11)) * (1 + i*y/2)
            const float cr = 1.0f + r11r, ci = r11i;
            const float cinv = frcp(cr * cr + ci * ci);
            const float trm = r01r * r10r - r01i * r10i;
            const float tim = r01r * r10i + r01i * r10r;
            const float qr = (trm * cr + tim * ci) * cinv;
            const float qi = (tim * cr - trm * ci) * cinv;
            const float kr = r00r - qr;
            const float ki = r00i - qi;
            const float hy = 0.5f * y;
            float fr = kr - ki * hy;
            float fi = ki + kr * hy;
            if (l == 0 || l == MM) fi = 0.0f;           // DC/Nyquist imag dropped
            g_X[h * LF + l] = make_float2(fr, fi);
        }
    }
}

// ============================================================================
// Kernel B: packed real inverse FFT. irfft-4096 via complex iFFT-2048.
// Z[k] = (X[k]+conj(X[M-k])) + i*w^k*(X[k]-conj(X[M-k])),  w = e^{+2pi i/4096}
// z = sum_k Z[k] e^{+2pi i nk/M};  out[2n] = Re(z[n])/L, out[2n+1] = Im(z[n])/L
// grid HH, block 512.
// ============================================================================
__global__ __launch_bounds__(512) void s4_fft(float* __restrict__ out)
{
    __shared__ float2 spec[MM];        // 16 KB
    __shared__ float2 tw[1025];        // exp(+i*pi*j/2048), j=0..1024

    const int h   = blockIdx.x;
    const int tid = threadIdx.x;

    for (int j = tid; j <= 1024; j += 512) {
        float s, c;
        sincosf((float)j * (3.14159265358979323846f / 2048.0f), &s, &c);
        tw[j] = make_float2(c, s);
    }
    __syncthreads();

    // build Z, store bit-reversed (folds the bit-reversal pass into the load)
    const float2* Xh = &g_X[h * LF];
    for (int k = tid; k < MM; k += 512) {
        const float2 Xk = Xh[k];
        const float2 Xm = Xh[MM - k];
        float2 w;
        if (k <= 1024) w = tw[k];
        else { const float2 t = tw[k - 1024]; w = make_float2(-t.y, t.x); }  // i*t
        const float arr = Xk.x + Xm.x, aii = Xk.y - Xm.y;   // X[k]+conj(Xm)
        const float brr = Xk.x - Xm.x, bii = Xk.y + Xm.y;   // X[k]-conj(Xm)
        // Z = a + i*w*b
        const float zr = arr - (w.x * bii + w.y * brr);
        const float zi = aii + (w.x * brr - w.y * bii);
        spec[__brev(k) >> 21] = make_float2(zr, zi);
    }
    __syncthreads();

    // fused radix-4 DIT passes: stage pairs (1,2),(3,4),(5,6),(7,8),(9,10)
    #pragma unroll
    for (int s = 1; s <= 9; s += 2) {
        const int hh = 1 << (s - 1);
        const int q  = tid;                       // 512 butterflies per pass
        const int j  = q & (hh - 1);
        const int bb = ((q >> (s - 1)) << (s + 1)) + j;
        const int i0 = bb, i1 = bb + hh, i2 = bb + 2 * hh, i3 = bb + 3 * hh;

        const float2 w2 = tw[j << (11 - s)];      // W_M^(j*2^(10-s)), idx<=1024
        const float w1x = w2.x * w2.x - w2.y * w2.y;
        const float w1y = 2.0f * w2.x * w2.y;

        const float2 x0 = spec[i0], x1 = spec[i1], x2 = spec[i2], x3 = spec[i3];

        const float t1x = w1x * x1.x - w1y * x1.y, t1y = w1x * x1.y + w1y * x1.x;
        const float a0x = x0.x + t1x, a0y = x0.y + t1y;
        const float a1x = x0.x - t1x, a1y = x0.y - t1y;
        const float t3x = w1x * x3.x - w1y * x3.y, t3y = w1x * x3.y + w1y * x3.x;
        const float a2x = x2.x + t3x, a2y = x2.y + t3y;
        const float a3x = x2.x - t3x, a3y = x2.y - t3y;

        const float t2x = w2.x * a2x - w2.y * a2y, t2y = w2.x * a2y + w2.y * a2x;
        const float c3x = w2.x * a3x - w2.y * a3y, c3y = w2.x * a3y + w2.y * a3x;

        __syncthreads();   // protect reads of previous pass (first pass: Z build)
        spec[i0] = make_float2(a0x + t2x, a0y + t2y);
        spec[i2] = make_float2(a0x - t2x, a0y - t2y);
        spec[i1] = make_float2(a1x - c3y, a1y + c3x);
        spec[i3] = make_float2(a1x + c3y, a1y - c3x);
        __syncthreads();
    }

    // final radix-2 stage (s=11): butterflies (j, j+1024), twiddle W_M^j
    for (int j = tid; j < 1024; j += 512) {
        float2 w;
        const int t = 2 * j;
        if (t <= 1024) w = tw[t];
        else { const float2 u = tw[t - 1024]; w = make_float2(-u.y, u.x); }
        const float2 a = spec[j];
        const float2 b = spec[j + 1024];
        const float trr = w.x * b.x - w.y * b.y;
        const float tii = w.x * b.y + w.y * b.x;
        spec[j]        = make_float2(a.x + trr, a.y + tii);
        spec[j + 1024] = make_float2(a.x - trr, a.y - tii);
    }
    __syncthreads();

    // unpack: out[h][2n] = Re(z[n])/L, out[h][2n+1] = Im(z[n])/L
    float2* out2 = (float2*)(out + h * LL);
    const float scale = 1.0f / (float)LL;
    for (int n = tid; n < MM; n += 512) {
        const float2 z = spec[n];
        out2[n] = make_float2(z.x * scale, z.y * scale);
    }
}

extern "C" void kernel_launch(void* const* d_in, const int* in_sizes, int n_in,
                              void* d_out, int out_size)
{
    (void)in_sizes; (void)n_in; (void)out_size;
    dim3 gridA(HH, 2);
    s4_cauchy<<<gridA, 256>>>(
        (const float*)d_in[0],   // A_real (H, N)
        (const float*)d_in[1],   // A_imag (H, N)
        (const float*)d_in[2],   // B (1, H, N, 2)
        (const float*)d_in[3],   // C (1, H, N, 2)
        (const float*)d_in[4],   // P (1, H, N, 2)
        (const float*)d_in[5]);  // inv_dt (H,)
    s4_fft<<<HH, 512>>>((float*)d_out);
}

// round 4
// speedup vs baseline: 1.8010x; 1.1217x over previous
#include <cuda_runtime.h>
#include <math.h>

#define HH 512
#define NN 64
#define LL 4096
#define MM 2048
#define LF 2049

typedef unsigned long long ull;

__device__ float2 g_X[HH * LF];   // Cauchy output spectrum X[h][l], l=0..2048

__device__ __forceinline__ ull f2_fma(ull a, ull b, ull c) {
    ull d; asm("fma.rn.f32x2 %0, %1, %2, %3;" : "=l"(d) : "l"(a), "l"(b), "l"(c)); return d;
}
__device__ __forceinline__ ull f2_mul(ull a, ull b) {
    ull d; asm("mul.rn.f32x2 %0, %1, %2;" : "=l"(d) : "l"(a), "l"(b)); return d;
}
__device__ __forceinline__ ull f2_add(ull a, ull b) {
    ull d; asm("add.rn.f32x2 %0, %1, %2;" : "=l"(d) : "l"(a), "l"(b)); return d;
}
__device__ __forceinline__ ull f2_pack(float lo, float hi) {
    ull d; asm("mov.b64 %0, {%1, %2};" : "=l"(d) : "f"(lo), "f"(hi)); return d;
}
__device__ __forceinline__ float2 f2_unpack(ull a) {
    float lo, hi; asm("mov.b64 {%0, %1}, %2;" : "=f"(lo), "=f"(hi) : "l"(a));
    return make_float2(lo, hi);
}
__device__ __forceinline__ float frcp(float x) {
    float r; asm("rcp.approx.f32 %0, %1;" : "=f"(r) : "f"(x)); return r;
}

// ============================================================================
// Kernel A: Cauchy sums -> X[h][l].  grid (HH, 4), block 128.
// Thread handles 4 bins: l = y*512 + tid + {0,128,256,384}.
// Thread (y==3, tid==0) additionally handles l=2048 (scalar).
// ============================================================================
__global__ __launch_bounds__(128) void s4_cauchy(
    const float* __restrict__ A_real,
    const float* __restrict__ A_imag,
    const float* __restrict__ Bm,
    const float* __restrict__ Cm,
    const float* __restrict__ Pm,
    const float* __restrict__ inv_dt)
{
    // per n-pair: 9 ulonglong2 = (m,c2),(p00,qc00),(q00,npc00),(p01,qc01),
    //             (q01,npc01),(p10,qc10),(q10,npc10),(p11,qc11),(q11,npc11)
    __shared__ ulonglong2 s_coef[NN / 2][9];

    const int h   = blockIdx.x;
    const int tid = threadIdx.x;

    if (tid < NN) {
        const int n  = tid;
        const float dt = expf(inv_dt[h]);
        const float ar = -expf(A_real[h * NN + n]) * dt;   // Re(A_dt)
        const float ai =  A_imag[h * NN + n] * dt;         // Im(A_dt)

        const int base = (h * NN + n) * 2;
        const float bx = Bm[base], by = Bm[base + 1];
        const float cx = Cm[base], cy = Cm[base + 1];
        const float px = Pm[base], py = Pm[base + 1];

        float vr[4], vi[4];
        vr[0] = (bx * cx - by * cy) * dt;  vi[0] = (bx * cy + by * cx) * dt;
        vr[1] = (bx * px + by * py) * dt;  vi[1] = (by * px - bx * py) * dt;
        vr[2] = (px * cx - py * cy) * dt;  vi[2] = (px * cy + py * cx) * dt;
        vr[3] = (px * px + py * py) * dt;  vi[3] = 0.0f;

        float* c = (float*)&s_coef[n >> 1][0];
        const int o = n & 1;
        const float ccoef = -2.0f * ar;
        c[0 + o] = ar * ar + ai * ai;                   // m
        c[2 + o] = ccoef * ccoef;                       // c^2
        #pragma unroll
        for (int ab = 0; ab < 4; ab++) {
            const float p = -2.0f * (vr[ab] * ar + vi[ab] * ai);
            const float q =  2.0f * vr[ab];
            const int bo = 4 + ab * 8;
            c[bo + 0 + o] = p;
            c[bo + 2 + o] = q * ccoef;                  // qc
            c[bo + 4 + o] = q;
            c[bo + 6 + o] = -p * ccoef;                 // npc
        }
    }
    __syncthreads();

    const float ANG = 3.14159265358979323846f / 4096.0f;
    const int base_l = blockIdx.y * 512 + tid;

    float yv[4];
    ull y2v[4], ny2v[4];
    #pragma unroll
    for (int b = 0; b < 4; b++) {
        const float y = 2.0f * tanf((float)(base_l + b * 128) * ANG);
        yv[b] = y;
        y2v[b]  = f2_pack(y * y, y * y);
        ny2v[b] = y2v[b] ^ 0x8000000080000000ULL;
    }

    ull accr[4][4], acci[4][4];   // [bin][ab]
    #pragma unroll
    for (int b = 0; b < 4; b++)
        #pragma unroll
        for (int ab = 0; ab < 4; ab++) { accr[b][ab] = 0; acci[b][ab] = 0; }

    #pragma unroll 4
    for (int k = 0; k < NN / 2; k++) {
        const ulonglong2* cc = &s_coef[k][0];
        const ulonglong2 c0 = cc[0];                    // (m, c2)

        ull dinv[4], y2inv[4], invv[4];
        #pragma unroll
        for (int b = 0; b < 4; b++) {
            const ull dr  = f2_add(c0.x, ny2v[b]);
            const ull mag = f2_fma(dr, dr, f2_mul(c0.y, y2v[b]));
            const float2 m = f2_unpack(mag);
            const ull inv = f2_pack(frcp(m.x), frcp(m.y));
            invv[b]  = inv;
            dinv[b]  = f2_mul(dr, inv);
            y2inv[b] = f2_mul(y2v[b], inv);
        }

        #pragma unroll
        for (int ab = 0; ab < 4; ab++) {
            const ulonglong2 ca = cc[1 + 2 * ab];       // (p, qc)
            const ulonglong2 cb = cc[2 + 2 * ab];       // (q, npc)
            #pragma unroll
            for (int b = 0; b < 4; b++) {
                accr[b][ab] = f2_fma(ca.x, dinv[b], f2_fma(ca.y, y2inv[b], accr[b][ab]));
                acci[b][ab] = f2_fma(cb.x, dinv[b], f2_fma(cb.y, invv[b],  acci[b][ab]));
            }
        }
    }

    // epilogue per bin
    #pragma unroll
    for (int b = 0; b < 4; b++) {
        const float y = yv[b];
        const int   l = base_l + b * 128;
        const float2 sr0 = f2_unpack(accr[b][0]), si0 = f2_unpack(acci[b][0]);
        const float2 sr1 = f2_unpack(accr[b][1]), si1 = f2_unpack(acci[b][1]);
        const float2 sr2 = f2_unpack(accr[b][2]), si2 = f2_unpack(acci[b][2]);
        const float2 sr3 = f2_unpack(accr[b][3]), si3 = f2_unpack(acci[b][3]);
        const float r00r = sr0.x + sr0.y, r00i = (si0.x + si0.y) * y;
        const float r01r = sr1.x + sr1.y, r01i = (si1.x + si1.y) * y;
        const float r10r = sr2.x + sr2.y, r10i = (si2.x + si2.y) * y;
        const float r11r = sr3.x + sr3.y, r11i = (si3.x + si3.y) * y;

        const float cr = 1.0f + r11r, ci = r11i;
        const float cinv = frcp(cr * cr + ci * ci);
        const float trm = r01r * r10r - r01i * r10i;
        const float tim = r01r * r10i + r01i * r10r;
        const float qr = (trm * cr + tim * ci) * cinv;
        const float qi = (tim * cr - trm * ci) * cinv;
        const float kr = r00r - qr;
        const float ki = r00i - qi;
        const float hy = 0.5f * y;
        float fr = kr - ki * hy;
        float fi = ki + kr * hy;
        if (l == 0) fi = 0.0f;
        g_X[h * LF + l] = make_float2(fr, fi);
    }

    // tail bin l = 2048 (scalar, one thread chip-wide per h)
    if (blockIdx.y == 3 && tid == 0) {
        const float y  = 2.0f * tanf(2048.0f * ANG);
        const float y2 = y * y;
        float rr[4] = {0, 0, 0, 0}, riy[4] = {0, 0, 0, 0};
        for (int n = 0; n < NN; n++) {
            const float* c = (const float*)&s_coef[n >> 1][0];
            const int o = n & 1;
            const float m  = c[0 + o];
            const float c2 = c[2 + o];
            const float dr = m - y2;
            const float inv = frcp(dr * dr + c2 * y2);
            const float dinv = dr * inv;
            const float y2inv = y2 * inv;
            #pragma unroll
            for (int ab = 0; ab < 4; ab++) {
                const int bo = 4 + ab * 8;
                rr[ab]  += c[bo + 0 + o] * dinv + c[bo + 2 + o] * y2inv;
                riy[ab] += c[bo + 4 + o] * dinv + c[bo + 6 + o] * inv;
            }
        }
        const float r00r = rr[0], r00i = riy[0] * y;
        const float r01r = rr[1], r01i = riy[1] * y;
        const float r10r = rr[2], r10i = riy[2] * y;
        const float r11r = rr[3], r11i = riy[3] * y;
        const float cr = 1.0f + r11r, ci = r11i;
        const float cinv = frcp(cr * cr + ci * ci);
        const float trm = r01r * r10r - r01i * r10i;
        const float tim = r01r * r10i + r01i * r10r;
        const float qr = (trm * cr + tim * ci) * cinv;
        const float qi = (tim * cr - trm * ci) * cinv;
        const float kr = r00r - qr;
        const float ki = r00i - qi;
        const float fr = kr - ki * (0.5f * y);
        g_X[h * LF + 2048] = make_float2(fr, 0.0f);
    }
}

// ============================================================================
// Kernel B: packed real inverse FFT (irfft-4096 via complex iFFT-2048),
// bank-conflict-free via padded shared indexing. grid HH, block 512.
// ============================================================================
#define IDX(i) ((i) + ((i) >> 5))

__global__ __launch_bounds__(512) void s4_fft(float* __restrict__ out)
{
    __shared__ float2 spec[MM + MM / 32];   // padded: 16.5 KB
    __shared__ float2 tw[1025];             // exp(+i*pi*j/2048), j=0..1024

    const int h   = blockIdx.x;
    const int tid = threadIdx.x;

    for (int j = tid; j <= 1024; j += 512) {
        float s, c;
        sincosf((float)j * (3.14159265358979323846f / 2048.0f), &s, &c);
        tw[j] = make_float2(c, s);
    }
    __syncthreads();

    // build Z (packing step), store bit-reversed
    const float2* Xh = &g_X[h * LF];
    for (int k = tid; k < MM; k += 512) {
        const float2 Xk = Xh[k];
        const float2 Xm = Xh[MM - k];
        float2 w;
        if (k <= 1024) w = tw[k];
        else { const float2 t = tw[k - 1024]; w = make_float2(-t.y, t.x); }
        const float arr = Xk.x + Xm.x, aii = Xk.y - Xm.y;
        const float brr = Xk.x - Xm.x, bii = Xk.y + Xm.y;
        const float zr = arr - (w.x * bii + w.y * brr);
        const float zi = aii + (w.x * brr - w.y * bii);
        spec[IDX(__brev(k) >> 21)] = make_float2(zr, zi);
    }
    __syncthreads();

    // fused radix-4 DIT passes: stage pairs (1,2),(3,4),(5,6),(7,8),(9,10)
    #pragma unroll
    for (int s = 1; s <= 9; s += 2) {
        const int hh = 1 << (s - 1);
        const int q  = tid;
        const int j  = q & (hh - 1);
        const int bb = ((q >> (s - 1)) << (s + 1)) + j;
        const int i0 = IDX(bb), i1 = IDX(bb + hh), i2 = IDX(bb + 2 * hh), i3 = IDX(bb + 3 * hh);

        const float2 w2 = tw[j << (11 - s)];
        const float w1x = w2.x * w2.x - w2.y * w2.y;
        const float w1y = 2.0f * w2.x * w2.y;

        const float2 x0 = spec[i0], x1 = spec[i1], x2 = spec[i2], x3 = spec[i3];

        const float t1x = w1x * x1.x - w1y * x1.y, t1y = w1x * x1.y + w1y * x1.x;
        const float a0x = x0.x + t1x, a0y = x0.y + t1y;
        const float a1x = x0.x - t1x, a1y = x0.y - t1y;
        const float t3x = w1x * x3.x - w1y * x3.y, t3y = w1x * x3.y + w1y * x3.x;
        const float a2x = x2.x + t3x, a2y = x2.y + t3y;
        const float a3x = x2.x - t3x, a3y = x2.y - t3y;

        const float t2x = w2.x * a2x - w2.y * a2y, t2y = w2.x * a2y + w2.y * a2x;
        const float c3x = w2.x * a3x - w2.y * a3y, c3y = w2.x * a3y + w2.y * a3x;

        __syncthreads();
        spec[i0] = make_float2(a0x + t2x, a0y + t2y);
        spec[i2] = make_float2(a0x - t2x, a0y - t2y);
        spec[i1] = make_float2(a1x - c3y, a1y + c3x);
        spec[i3] = make_float2(a1x + c3y, a1y - c3x);
        __syncthreads();
    }

    // final radix-2 stage (s=11)
    for (int j = tid; j < 1024; j += 512) {
        float2 w;
        const int t = 2 * j;
        if (t <= 1024) w = tw[t];
        else { const float2 u = tw[t - 1024]; w = make_float2(-u.y, u.x); }
        const float2 a = spec[IDX(j)];
        const float2 b = spec[IDX(j + 1024)];
        const float trr = w.x * b.x - w.y * b.y;
        const float tii = w.x * b.y + w.y * b.x;
        spec[IDX(j)]        = make_float2(a.x + trr, a.y + tii);
        spec[IDX(j + 1024)] = make_float2(a.x - trr, a.y - tii);
    }
    __syncthreads();

    // unpack: out[h][2n] = Re(z[n])/L, out[h][2n+1] = Im(z[n])/L
    float2* out2 = (float2*)(out + h * LL);
    const float scale = 1.0f / (float)LL;
    for (int n = tid; n < MM; n += 512) {
        const float2 z = spec[IDX(n)];
        out2[n] = make_float2(z.x * scale, z.y * scale);
    }
}

extern "C" void kernel_launch(void* const* d_in, const int* in_sizes, int n_in,
                              void* d_out, int out_size)
{
    (void)in_sizes; (void)n_in; (void)out_size;
    dim3 gridA(HH, 4);
    s4_cauchy<<<gridA, 128>>>(
        (const float*)d_in[0],   // A_real (H, N)
        (const float*)d_in[1],   // A_imag (H, N)
        (const float*)d_in[2],   // B (1, H, N, 2)
        (const float*)d_in[3],   // C (1, H, N, 2)
        (const float*)d_in[4],   // P (1, H, N, 2)
        (const float*)d_in[5]);  // inv_dt (H,)
    s4_fft<<<HH, 512>>>((float*)d_out);
}